// round 4
// baseline (speedup 1.0000x reference)
#include <cuda_runtime.h>
#include <cuda_bf16.h>

// EntropyLoss: x [R=65536, C=1024] f32 -> scalar.
//   norm_j = sqrt(sum_r x[r][j]^2); p = x / max(norm,1e-12)
//   out    = mean_r( -sum_j p*log(p+1e-8) )
//
// Single persistent kernel, two passes over HBM separated by an in-kernel
// grid barrier (spin; residency-guaranteed single wave). Pass 2 walks each
// block's chunk BACKWARD to harvest L1+L2 residue from pass 1 (nothing
// intervenes between passes anymore). The last block to finish writes the
// output and restores all __device__ scratch to zero for the next replay
// (globals are zero at module load -> every launch sees the same state).

#define COLS    1024
#define VCOLS   256              // COLS/4 float4 lanes
#define THREADS 512
#define GRID    296              // 2 blocks/SM x 148 SMs: all co-resident

__device__ float    d_colsumsq[COLS];       // zero-init at load; re-zeroed each launch
__device__ double   d_entropy_acc;
__device__ unsigned d_bar_arrive;
__device__ unsigned d_bar_release;
__device__ unsigned d_done;

__global__ __launch_bounds__(THREADS, 2) void entropy_fused_kernel(
    const float* __restrict__ x, float* __restrict__ out, int rows)
{
    __shared__ float    sinv[COLS];
    __shared__ float    sred[THREADS / 32];
    __shared__ unsigned s_last;

    const int t     = threadIdx.x;
    const int lane4 = t & (VCOLS - 1);      // which float4 column group
    const int rsub  = t >> 8;               // 0 or 1: row parity within block
    const int G     = gridDim.x;
    const float4* __restrict__ xv = (const float4*)x;

    const long r0 = ((long)rows * blockIdx.x) / G;
    const long r1 = ((long)rows * (blockIdx.x + 1)) / G;

    // ---------------- Pass 1: column sum-of-squares (forward walk) ----------
    float s0 = 0.f, s1 = 0.f, s2 = 0.f, s3 = 0.f;
#pragma unroll 4
    for (long r = r0 + rsub; r < r1; r += 2) {
        float4 v = xv[r * VCOLS + lane4];
        s0 = fmaf(v.x, v.x, s0);
        s1 = fmaf(v.y, v.y, s1);
        s2 = fmaf(v.z, v.z, s2);
        s3 = fmaf(v.w, v.w, s3);
    }
    atomicAdd(&d_colsumsq[4 * lane4 + 0], s0);
    atomicAdd(&d_colsumsq[4 * lane4 + 1], s1);
    atomicAdd(&d_colsumsq[4 * lane4 + 2], s2);
    atomicAdd(&d_colsumsq[4 * lane4 + 3], s3);

    // ---------------- Grid barrier (all 296 blocks resident: no deadlock) --
    __syncthreads();
    if (t == 0) {
        __threadfence();
        unsigned arrived = atomicAdd(&d_bar_arrive, 1u) + 1u;
        if (arrived == (unsigned)G) {
            __threadfence();
            atomicExch(&d_bar_release, 1u);
        } else {
            while (atomicAdd(&d_bar_release, 0u) == 0u) __nanosleep(64);
        }
        __threadfence();
    }
    __syncthreads();

    // ---------------- Column inverse norms into smem -----------------------
    for (int i = t; i < COLS; i += THREADS) {
        float n = sqrtf(d_colsumsq[i]);
        sinv[i] = 1.0f / fmaxf(n, 1e-12f);
    }
    __syncthreads();

    // ---------------- Pass 2: entropy (BACKWARD walk: L1/L2 residue) -------
    const float4 inv = ((const float4*)sinv)[lane4];
    const float eps = 1e-8f;
    float acc = 0.f;
#pragma unroll 4
    for (long r = r1 - 1 - rsub; r >= r0; r -= 2) {
        float4 v = xv[r * VCOLS + lane4];
        float p0 = v.x * inv.x;
        float p1 = v.y * inv.y;
        float p2 = v.z * inv.z;
        float p3 = v.w * inv.w;
        acc = fmaf(p0, __logf(p0 + eps), acc);
        acc = fmaf(p1, __logf(p1 + eps), acc);
        acc = fmaf(p2, __logf(p2 + eps), acc);
        acc = fmaf(p3, __logf(p3 + eps), acc);
    }

    // warp + block reduce, one double atomic per block
#pragma unroll
    for (int off = 16; off > 0; off >>= 1)
        acc += __shfl_xor_sync(0xFFFFFFFFu, acc, off);
    if ((t & 31) == 0) sred[t >> 5] = acc;
    __syncthreads();
    if (t < 32) {
        float v = (t < THREADS / 32) ? sred[t] : 0.f;
#pragma unroll
        for (int off = 8; off > 0; off >>= 1)
            v += __shfl_xor_sync(0xFFFFFFFFu, v, off);
        if (t == 0) atomicAdd(&d_entropy_acc, (double)v);
    }

    // ---------------- Completion: last block writes out + restores zeros ---
    if (t == 0) {
        __threadfence();
        unsigned done = atomicAdd(&d_done, 1u) + 1u;
        s_last = (done == (unsigned)G) ? 1u : 0u;
    }
    __syncthreads();
    if (s_last) {
        // Every other block has fully finished (read colsumsq, added its
        // entropy). Safe to write the result and restore scratch to zero.
        for (int i = t; i < COLS; i += THREADS) d_colsumsq[i] = 0.f;
        if (t == 0) {
            double e = atomicAdd(&d_entropy_acc, 0.0);  // coherent read
            out[0] = (float)(-e / (double)rows);
            d_entropy_acc = 0.0;
            atomicExch(&d_bar_arrive, 0u);
            atomicExch(&d_bar_release, 0u);
            atomicExch(&d_done, 0u);
            __threadfence();
        }
    }
}

extern "C" void kernel_launch(void* const* d_in, const int* in_sizes, int n_in,
                              void* d_out, int out_size) {
    const float* x = (const float*)d_in[0];
    float* out = (float*)d_out;
    const int rows = in_sizes[0] / COLS;    // 65536
    entropy_fused_kernel<<<GRID, THREADS>>>(x, out, rows);
}

// round 6
// speedup vs baseline: 1.9140x; 1.9140x over previous
#include <cuda_runtime.h>
#include <cuda_bf16.h>

// EntropyLoss: x [R=65536, C=1024] f32 -> scalar.
//   n_j = max(sqrt(sum_r x^2), 1e-12); p = x/n; out = mean_r(-sum_j p*log(p+1e-8))
//
// ONE-PASS algebraic form (eps folded out; rel err ~5e-7 << 1e-3 tolerance):
//   out = -(1/R) * sum_j [ T_j*ln2 - S1_j*ln(n_j) ] / n_j
//   with per-column  S2 = sum x^2,  S1 = sum x,  T = sum x*log2(x)  (log2 units
//   so the hot loop is 1 raw MUFU LG2 per element; *ln2 once at the end).
// x*log2(x+1e-30) guards x==0 (term -> 0, matching reference's 0*log(eps)).
//
// Single launch: 296 blocks x 1024 threads, __launch_bounds__(1024,2) =>
// 2048 thr/SM (Round-4 evidence: DRAM% tracks resident warps) => hard 32-reg
// cap, so the hot loop is register-dieted: pointer walk + int trip counter,
// 6 f32 accumulators, no 64-bit index arithmetic in the loop.
// Thread owns one float2 column pair; the two row-parity partners merge in
// smem so each block issues 6 atomics per column pair. Last-done block
// finalizes in-kernel and restores all scratch to zero for graph replay.

#define COLS    1024
#define C2      512              // float2 column groups
#define THREADS 1024
#define GRID    296

__device__ float    d_S2[COLS];   // zero at module load; re-zeroed each launch
__device__ float    d_S1[COLS];
__device__ float    d_T[COLS];
__device__ unsigned d_done;

__global__ __launch_bounds__(THREADS, 2) void entropy_onepass_kernel(
    const float* __restrict__ x, float* __restrict__ out, int rows)
{
    __shared__ float  sm[3 * COLS];         // [s2 | s1 | t] partials from rsub=1
    __shared__ double sred[32];
    __shared__ bool   s_last;

    const int t    = threadIdx.x;
    const int c2   = t & (C2 - 1);          // which float2 column pair
    const int rsub = t >> 9;                // 0/1: row parity within block

    const long r0 = ((long)rows * blockIdx.x) / GRID;
    const long r1 = ((long)rows * (blockIdx.x + 1)) / GRID;
    // iterations for this parity: ceil((r1-r0-rsub)/2)
    int iters = (int)((r1 - r0 - rsub + 1) >> 1);
    const float2* __restrict__ p = (const float2*)x + (r0 + rsub) * C2 + c2;

    // ---- Single streaming pass: per-column S2, S1, T(log2 units) ----------
    float s2x = 0.f, s2y = 0.f, s1x = 0.f, s1y = 0.f, tx = 0.f, ty = 0.f;
#pragma unroll 8
    for (; iters > 0; --iters, p += 2 * C2) {
        float2 v = *p;
        s2x = fmaf(v.x, v.x, s2x);
        s2y = fmaf(v.y, v.y, s2y);
        s1x += v.x;
        s1y += v.y;
        tx  = fmaf(v.x, __log2f(v.x + 1e-30f), tx);
        ty  = fmaf(v.y, __log2f(v.y + 1e-30f), ty);
    }

    // ---- Merge row-parity partners in smem; rsub=0 does the atomics -------
    if (rsub) {
        sm[2 * c2]                = s2x;  sm[2 * c2 + 1]            = s2y;
        sm[COLS + 2 * c2]         = s1x;  sm[COLS + 2 * c2 + 1]     = s1y;
        sm[2 * COLS + 2 * c2]     = tx;   sm[2 * COLS + 2 * c2 + 1] = ty;
    }
    __syncthreads();
    if (!rsub) {
        atomicAdd(&d_S2[2 * c2],     s2x + sm[2 * c2]);
        atomicAdd(&d_S2[2 * c2 + 1], s2y + sm[2 * c2 + 1]);
        atomicAdd(&d_S1[2 * c2],     s1x + sm[COLS + 2 * c2]);
        atomicAdd(&d_S1[2 * c2 + 1], s1y + sm[COLS + 2 * c2 + 1]);
        atomicAdd(&d_T[2 * c2],      tx  + sm[2 * COLS + 2 * c2]);
        atomicAdd(&d_T[2 * c2 + 1],  ty  + sm[2 * COLS + 2 * c2 + 1]);
    }

    // ---- Last-done block finalizes (fence + counter pattern) --------------
    __threadfence();
    __syncthreads();
    if (t == 0) {
        unsigned done = atomicAdd(&d_done, 1u) + 1u;
        s_last = (done == (unsigned)gridDim.x);
    }
    __syncthreads();
    if (!s_last) return;

    __threadfence();
    // Thread t handles column t (1024 threads == 1024 columns).
    float S2 = d_S2[t], S1 = d_S1[t], T = d_T[t];
    float n  = fmaxf(sqrtf(S2), 1e-12f);
    double contrib = ((double)T * 0.6931471805599453
                      - (double)S1 * (double)__logf(n)) / (double)n;

    // block-reduce 1024 doubles
#pragma unroll
    for (int off = 16; off > 0; off >>= 1)
        contrib += __shfl_xor_sync(0xFFFFFFFFu, contrib, off);
    if ((t & 31) == 0) sred[t >> 5] = contrib;
    __syncthreads();
    if (t < 32) {
        double v = sred[t];
#pragma unroll
        for (int off = 16; off > 0; off >>= 1)
            v += __shfl_xor_sync(0xFFFFFFFFu, v, off);
        if (t == 0) out[0] = (float)(-v / (double)rows);
    }

    // restore scratch to zero for the next graph replay
    d_S2[t] = 0.f; d_S1[t] = 0.f; d_T[t] = 0.f;
    if (t == 0) d_done = 0u;
}

extern "C" void kernel_launch(void* const* d_in, const int* in_sizes, int n_in,
                              void* d_out, int out_size) {
    const float* x = (const float*)d_in[0];
    float* out = (float*)d_out;
    const int rows = in_sizes[0] / COLS;    // 65536
    entropy_onepass_kernel<<<GRID, THREADS>>>(x, out, rows);
}

// round 7
// speedup vs baseline: 1.9343x; 1.0106x over previous
#include <cuda_runtime.h>
#include <cuda_bf16.h>

// EntropyLoss: x [R=65536, C=1024] f32 -> scalar.
//   n_j = max(sqrt(sum_r x^2), 1e-12); p = x/n; out = mean_r(-sum_j p*log(p+1e-8))
//
// ONE-PASS algebraic form (eps folded out; measured rel err 5.0e-7):
//   out = -(1/R) * sum_j [ T_j*ln2 - S1_j*ln(n_j) ] / n_j
//   per column:  S2 = sum x^2,  S1 = sum x,  T = sum x*log2(x)   (log2 units)
// x*log2(x+1e-30) guards x==0 (term -> 0, matching reference 0*log(eps)).
//
// Round 7: float4 loads (LDG.128) to halve load-instruction count and loop
// overhead per byte (R6: DRAM=61%, issue=35.5%, occ=96%). Register diet to
// hold the 32-reg cap at 2048 thr/SM: 12 accumulators + pointer walk + int
// counter; block-level merge via smem ATOMICS (no extra live registers).
// Thread owns one float4 column group (4 columns); 4 row-parity threads per
// group stride rows by 4. Last-done block finalizes in-kernel and re-zeroes
// all scratch for graph replay.

#define COLS    1024
#define C4      256              // float4 column groups
#define THREADS 1024
#define GRID    296              // 2 blocks/SM x 148 SMs

__device__ float    d_S2[COLS];   // zero at module load; re-zeroed each launch
__device__ float    d_S1[COLS];
__device__ float    d_T[COLS];
__device__ unsigned d_done;

__global__ __launch_bounds__(THREADS, 2) void entropy_onepass_kernel(
    const float* __restrict__ x, float* __restrict__ out, int rows)
{
    __shared__ float  s_s2[COLS], s_s1[COLS], s_t[COLS];
    __shared__ double sred[32];
    __shared__ bool   s_last;

    const int t    = threadIdx.x;
    const int c4   = t & (C4 - 1);          // which float4 column group
    const int rsub = t >> 8;                // 0..3: row parity within block

    // zero smem accumulators (3 stores/thread)
    s_s2[t & 1023] = 0.f;                   // t covers 0..1023 == COLS
    s_s1[t] = 0.f;
    s_t[t]  = 0.f;

    const long r0 = ((long)rows * blockIdx.x) / GRID;
    const long r1 = ((long)rows * (blockIdx.x + 1)) / GRID;
    int iters = (int)((r1 - r0 - rsub + 3) >> 2);   // rows == rsub (mod 4) in chunk
    const float4* __restrict__ p = (const float4*)x + (r0 + rsub) * C4 + c4;

    // ---- Single streaming pass: per-column S2, S1, T(log2 units) ----------
    float a0 = 0.f, a1 = 0.f, a2 = 0.f, a3 = 0.f;   // S2
    float b0 = 0.f, b1 = 0.f, b2 = 0.f, b3 = 0.f;   // S1
    float t0 = 0.f, t1 = 0.f, t2 = 0.f, t3 = 0.f;   // T
#pragma unroll 4
    for (; iters > 0; --iters, p += 4 * C4) {
        float4 v = *p;
        a0 = fmaf(v.x, v.x, a0);
        a1 = fmaf(v.y, v.y, a1);
        a2 = fmaf(v.z, v.z, a2);
        a3 = fmaf(v.w, v.w, a3);
        b0 += v.x; b1 += v.y; b2 += v.z; b3 += v.w;
        t0 = fmaf(v.x, __log2f(v.x + 1e-30f), t0);
        t1 = fmaf(v.y, __log2f(v.y + 1e-30f), t1);
        t2 = fmaf(v.z, __log2f(v.z + 1e-30f), t2);
        t3 = fmaf(v.w, __log2f(v.w + 1e-30f), t3);
    }
    __syncthreads();   // smem zeros visible

    // ---- Block merge via smem atomics (spread addresses: ~no conflicts) ---
    const int c = 4 * c4;
    atomicAdd(&s_s2[c + 0], a0); atomicAdd(&s_s2[c + 1], a1);
    atomicAdd(&s_s2[c + 2], a2); atomicAdd(&s_s2[c + 3], a3);
    atomicAdd(&s_s1[c + 0], b0); atomicAdd(&s_s1[c + 1], b1);
    atomicAdd(&s_s1[c + 2], b2); atomicAdd(&s_s1[c + 3], b3);
    atomicAdd(&s_t[c + 0],  t0); atomicAdd(&s_t[c + 1],  t1);
    atomicAdd(&s_t[c + 2],  t2); atomicAdd(&s_t[c + 3],  t3);
    __syncthreads();

    // thread t owns column t for the global merge (3 atomics/thread)
    atomicAdd(&d_S2[t], s_s2[t]);
    atomicAdd(&d_S1[t], s_s1[t]);
    atomicAdd(&d_T[t],  s_t[t]);

    // ---- Last-done block finalizes (fence + counter) ----------------------
    __threadfence();
    __syncthreads();
    if (t == 0) {
        unsigned done = atomicAdd(&d_done, 1u) + 1u;
        s_last = (done == (unsigned)gridDim.x);
    }
    __syncthreads();
    if (!s_last) return;

    __threadfence();
    float S2 = d_S2[t], S1 = d_S1[t], T = d_T[t];
    float n  = fmaxf(sqrtf(S2), 1e-12f);
    double contrib = ((double)T * 0.6931471805599453
                      - (double)S1 * (double)__logf(n)) / (double)n;

#pragma unroll
    for (int off = 16; off > 0; off >>= 1)
        contrib += __shfl_xor_sync(0xFFFFFFFFu, contrib, off);
    if ((t & 31) == 0) sred[t >> 5] = contrib;
    __syncthreads();
    if (t < 32) {
        double v = sred[t];
#pragma unroll
        for (int off = 16; off > 0; off >>= 1)
            v += __shfl_xor_sync(0xFFFFFFFFu, v, off);
        if (t == 0) out[0] = (float)(-v / (double)rows);
    }

    // restore scratch to zero for the next graph replay
    d_S2[t] = 0.f; d_S1[t] = 0.f; d_T[t] = 0.f;
    if (t == 0) d_done = 0u;
}

extern "C" void kernel_launch(void* const* d_in, const int* in_sizes, int n_in,
                              void* d_out, int out_size) {
    const float* x = (const float*)d_in[0];
    float* out = (float*)d_out;
    const int rows = in_sizes[0] / COLS;    // 65536
    entropy_onepass_kernel<<<GRID, THREADS>>>(x, out, rows);
}